// round 5
// baseline (speedup 1.0000x reference)
#include <cuda_runtime.h>

#define NB 4
#define NC 64
#define HW 40
#define KS 11
#define HP 30
#define PIX 1600          // 40*40
#define PW  112           // padded im2 row width in smem
#define POFF 32           // left pad
#define NDX 15            // dx shifts per block (4 groups: 15+15+15+14 live)
#define NG 8              // norm partial groups
#define OUTN (NB*HP*HP)

typedef unsigned long long ull;

__device__ unsigned g_enc[OUTN];
__device__ float    g_inv[OUTN];
__device__ float    g_part[NB*NG*PIX];

__device__ __forceinline__ unsigned encf(float f){
    int b = __float_as_int(f);
    return (unsigned)(b ^ ((b >> 31) | 0x80000000));
}

#define PACKF2(out, lo, hi) \
    asm("mov.b64 %0, {%1, %2};" : "=l"(out) : "f"(lo), "f"(hi))
#define UNPACKF2(lo, hi, in) \
    asm("mov.b64 {%0, %1}, %2;" : "=f"(lo), "=f"(hi) : "l"(in))
#define FMAF2(d, a, b, c) \
    asm("fma.rn.f32x2 %0, %1, %2, %3;" : "=l"(d) : "l"(a), "l"(b), "l"(c))

// ---------------- K0a: partial channel sum-of-squares ----------------
__global__ void __launch_bounds__(256) norm_part(const float* __restrict__ im1){
    int b = blockIdx.x, g = blockIdx.y;
    const float* base = im1 + ((size_t)b*NC + g*(NC/NG))*PIX;
    for (int p = threadIdx.x; p < PIX; p += 256){
        float acc = 0.f;
        #pragma unroll
        for (int c = 0; c < NC/NG; ++c){ float v = base[c*PIX + p]; acc += v*v; }
        g_part[(b*NG + g)*PIX + p] = acc;
    }
}

// ---------------- K0b: reduce partials + 11x11 box sum -> inv norm ----------------
__global__ void __launch_bounds__(1024) norm_reduce(){
    __shared__ float sA[PIX];
    __shared__ float sH[HW*HP];
    int b = blockIdx.x;
    int tid = threadIdx.x;
    for (int p = tid; p < PIX; p += 1024){
        float acc = 0.f;
        #pragma unroll
        for (int g = 0; g < NG; ++g) acc += g_part[(b*NG + g)*PIX + p];
        sA[p] = acc;
    }
    __syncthreads();
    for (int t = tid; t < HW*HP; t += 1024){
        int y = t / HP, lx = t - y*HP;
        const float* row = &sA[y*HW];
        float s = 0.f;
        #pragma unroll
        for (int j = 0; j < KS; ++j) s += row[lx + j];
        sH[y*HP + lx] = s;
    }
    __syncthreads();
    for (int t = tid; t < HP*HP; t += 1024){
        int ly = t / HP, lx = t - ly*HP;
        float s = 0.f;
        #pragma unroll
        for (int i = 0; i < KS; ++i) s += sH[(ly+i)*HP + lx];
        float nrm = sqrtf(s);
        g_inv[b*HP*HP + t] = 1.0f / fmaxf(nrm, 1e-4f);
        g_enc[b*HP*HP + t] = 0u;
    }
}

// ---------------- corr mainloop: templated on w-window shift SH ----------------
// SH = 3 + ((dxlo-3)&3): g0->3, g1->6, g2->5, g3->4
template<int SH>
__device__ __forceinline__ void run_channels(
    const float* __restrict__ g1, const float* __restrict__ g2,
    float* __restrict__ s2_0, float* __restrict__ s2_1,
    ull* q01, ull* q23,
    int tid, int n4, int a0, int d2)
{
    bool ld = (tid < n4);
    float4 aCur = make_float4(0,0,0,0), aNxt = aCur, wNxt = aCur;

    if (ld){
        aCur = ((const float4*)g1)[tid];
        float4 w0 = ((const float4*)g2)[tid];
        *(float4*)&s2_0[d2] = w0;
        aNxt = ((const float4*)(g1 + PIX))[tid];
        wNxt = ((const float4*)(g2 + PIX))[tid];
    }
    __syncthreads();   // buf0 staged; pads zeroed

    #pragma unroll 1
    for (int c = 0; c < NC; ++c){
        float* cur = (c & 1) ? s2_1 : s2_0;
        float* nxt = (c & 1) ? s2_0 : s2_1;

        if (c + 1 < NC && ld)
            *(float4*)&nxt[d2] = wNxt;            // stage channel c+1

        float4 aP = aNxt;
        if (c + 2 < NC && ld){                    // prefetch channel c+2
            aNxt = ((const float4*)(g1 + (c+2)*PIX))[tid];
            wNxt = ((const float4*)(g2 + (c+2)*PIX))[tid];
        }

        if (ld){
            float w[24];
            #pragma unroll
            for (int k = 0; k < 6; ++k){
                float4 tv = *(const float4*)&cur[a0 + 4*k];
                w[4*k+0]=tv.x; w[4*k+1]=tv.y; w[4*k+2]=tv.z; w[4*k+3]=tv.w;
            }
            ull axy, azw;
            PACKF2(axy, aCur.x, aCur.y);
            PACKF2(azw, aCur.z, aCur.w);
            ull wp[17];
            #pragma unroll
            for (int k = 0; k < 17; ++k)
                PACKF2(wp[k], w[SH + k], w[SH + k + 1]);
            #pragma unroll
            for (int d = 0; d < NDX; ++d){
                FMAF2(q01[d], axy, wp[d],   q01[d]);
                FMAF2(q23[d], azw, wp[d+2], q23[d]);
            }
        }
        aCur = aP;
        __syncthreads();   // reads of cur done before next iter overwrites it
    }
}

// ---------------- K1: displacement correlation + box sums + max ----------------
// grid: (4 dx-groups, 59 dy, 4 batch), 512 threads
__global__ void __launch_bounds__(512, 1) corr_kernel(const float* __restrict__ im1,
                                                      const float* __restrict__ im2){
    extern __shared__ float smem[];
    float* s2_0 = smem;                   // [40*112] zero-padded, buffer 0
    float* s2_1 = s2_0 + HW*PW;           // buffer 1
    float* sq   = s2_1 + HW*PW;           // [NDX*1600]
    float* sinv = sq + NDX*PIX;           // [900]

    int tid  = threadIdx.x;
    int gx   = blockIdx.x;
    int b    = blockIdx.z;
    int dy   = (int)blockIdx.y - 29;
    int dxlo = -29 + NDX*gx;

    // zero both padded im2 buffers; load inv-norm
    for (int i = tid; i < (2*HW*PW)/4; i += 512)
        ((float4*)s2_0)[i] = make_float4(0.f,0.f,0.f,0.f);
    for (int i = tid; i < HP*HP; i += 512) sinv[i] = g_inv[b*HP*HP + i];

    int y0 = max(0, -dy), y1 = min(HW, HW - dy);
    int nrows = y1 - y0;
    int n4 = nrows * 10;                  // active threads = float4 strips

    int sy = y0 + tid/10;
    int sx = (tid - (tid/10)*10) * 4;
    int i1 = sy*HW + sx;

    const float* g1 = im1 + (size_t)b*NC*PIX + y0*HW;
    const float* g2 = im2 + (size_t)b*NC*PIX + (y0+dy)*HW;

    int r2row = tid/10;
    int d2 = (y0+dy+r2row)*PW + POFF + (tid - r2row*10)*4;

    ull q01[NDX], q23[NDX];
    #pragma unroll
    for (int d = 0; d < NDX; ++d){ q01[d] = 0ull; q23[d] = 0ull; }

    // a0 aligned: dxlo - SH is a multiple of 4 by construction of SH
    switch (gx){
        case 0: run_channels<3>(g1,g2,s2_0,s2_1,q01,q23,tid,n4,(sy+dy)*PW+POFF+sx+dxlo-3,d2); break;
        case 1: run_channels<6>(g1,g2,s2_0,s2_1,q01,q23,tid,n4,(sy+dy)*PW+POFF+sx+dxlo-6,d2); break;
        case 2: run_channels<5>(g1,g2,s2_0,s2_1,q01,q23,tid,n4,(sy+dy)*PW+POFF+sx+dxlo-5,d2); break;
        default: run_channels<4>(g1,g2,s2_0,s2_1,q01,q23,tid,n4,(sy+dy)*PW+POFF+sx+dxlo-4,d2); break;
    }

    // dump accumulators
    if (tid < n4){
        #pragma unroll
        for (int d = 0; d < NDX; ++d){
            float x0,x1,x2,x3;
            UNPACKF2(x0,x1,q01[d]);
            UNPACKF2(x2,x3,q23[d]);
            *(float4*)&sq[d*PIX + i1] = make_float4(x0,x1,x2,x3);
        }
    }
    __syncthreads();

    // horizontal 11-sum (in place, cols 0..29)
    for (int t = tid; t < NDX*nrows; t += 512){
        int d = t / nrows;
        int y = y0 + (t - d*nrows);
        float* row = &sq[d*PIX + y*HW];
        float r[HW];
        #pragma unroll
        for (int k = 0; k < HW/4; ++k){
            float4 tv = *(const float4*)&row[4*k];
            r[4*k+0]=tv.x; r[4*k+1]=tv.y; r[4*k+2]=tv.z; r[4*k+3]=tv.w;
        }
        float s = 0.f;
        #pragma unroll
        for (int j = 0; j < KS; ++j) s += r[j];
        row[0] = s;
        #pragma unroll
        for (int lx = 1; lx < HP; ++lx){
            s += r[lx+KS-1] - r[lx-1];
            row[lx] = s;
        }
    }
    __syncthreads();

    // vertical 11-sum (in place)
    int ly0 = max(0, -dy);
    int nly = min(HP, HP - dy) - ly0;
    for (int t = tid; t < NDX*HP; t += 512){
        int d = t / HP, lx = t - (t/HP)*HP;
        float* colp = &sq[d*PIX + lx];
        int cnt = nly + KS - 1;
        float v[HW];
        #pragma unroll
        for (int i = 0; i < HW; ++i) v[i] = (i < cnt) ? colp[(ly0+i)*HW] : 0.f;
        float s = 0.f;
        #pragma unroll
        for (int j = 0; j < KS; ++j) s += v[j];
        #pragma unroll
        for (int o = 0; o < HP; ++o){
            if (o < nly) colp[(ly0+o)*HW] = s;
            if (o+1 < HP) s += v[o+KS] - v[o];
        }
    }
    __syncthreads();

    // per-output max over this block's dx set, one atomicMax per p
    unsigned* eout = &g_enc[b*HP*HP];
    for (int t = tid; t < HP*HP; t += 512){
        int py = t / HP, px = t - (t/HP)*HP;
        int ly = py - dy;
        if (ly < 0 || ly >= HP) continue;
        float m = -3.0e38f;
        bool any = false;
        #pragma unroll
        for (int d = 0; d < NDX; ++d){
            int dx = dxlo + d;
            int lx = px - dx;
            if (dx <= 29 && lx >= 0 && lx < HP){
                float v = sq[d*PIX + ly*HW + lx] * sinv[ly*HP + lx];
                m = fmaxf(m, v);
                any = true;
            }
        }
        if (any) atomicMax(&eout[t], encf(m));
    }
}

// ---------------- K2: decode ----------------
__global__ void decode_kernel(float* __restrict__ out){
    int t = blockIdx.x*blockDim.x + threadIdx.x;
    if (t < OUTN){
        unsigned e = g_enc[t];
        int v = (e & 0x80000000u) ? (int)(e ^ 0x80000000u) : ~(int)e;
        out[t] = __int_as_float(v);
    }
}

extern "C" void kernel_launch(void* const* d_in, const int* in_sizes, int n_in,
                              void* d_out, int out_size){
    (void)in_sizes; (void)n_in; (void)out_size;
    const float* im1 = (const float*)d_in[0];
    const float* im2 = (const float*)d_in[1];

    const int smem_bytes = (2*HW*PW + NDX*PIX + HP*HP) * (int)sizeof(float);
    cudaFuncSetAttribute(corr_kernel, cudaFuncAttributeMaxDynamicSharedMemorySize, smem_bytes);

    norm_part<<<dim3(NB, NG), 256>>>(im1);
    norm_reduce<<<NB, 1024>>>();
    corr_kernel<<<dim3(4, 59, NB), 512, smem_bytes>>>(im1, im2);
    decode_kernel<<<(OUTN + 255)/256, 256>>>((float*)d_out);
}